// round 3
// baseline (speedup 1.0000x reference)
#include <cuda_runtime.h>
#include <math.h>

#define S     8
#define H     128
#define BB    4096
#define GRID  296
#define NWARP 8
#define TOTAL_WARPS (GRID * NWARP)

// Scratch (no allocation allowed) — device globals, zero-initialized.
__device__ __align__(16) float g_new_slot[S * H];
__device__ __align__(16) float g_u1[H];
__device__ __align__(16) float g_u2[H];
__device__ __align__(16) float g_ctx[BB * H];
__device__ volatile unsigned g_flag_u;   // == gen+1 when u1/u2 ready
__device__ volatile unsigned g_flag_s;   // == gen+1 when new_slot ready
__device__ unsigned          g_bar_cnt;  // grid-barrier arrival counter
__device__ volatile unsigned g_gen;      // grid-barrier generation

__global__ __launch_bounds__(256, 2)
void fused_kernel(const float* __restrict__ memory,
                  const float* __restrict__ o_emb_w,
                  const float* __restrict__ o_emb_r,
                  const float* __restrict__ attn_W,
                  const float* __restrict__ sim_w,
                  const float* __restrict__ sim_b,
                  const float* __restrict__ forget_w,
                  const int*   __restrict__ o_rg_p,
                  const int*   __restrict__ d_rg,
                  float*       __restrict__ out)
{
    // 48KB static smem, time-shared: prep (block 0: sim_w cache) -> gemm (Ws+Cs)
    __shared__ float smem_buf[64 * H + 32 * H];   // 49152 B

    const int tid  = threadIdx.x;
    const int bx   = blockIdx.x;
    const int warp = tid >> 5;
    const int lane = tid & 31;

    // Generation read BEFORE any arrival: release for this launch cannot have
    // happened yet (it requires all blocks to arrive), so this is stable.
    const unsigned gen0 = g_gen;

    // ================= PREP (blocks 0 and 1) =================
    if (bx == 0) {
        // u1 = W @ sim_w[:H] (threads 0..127), u2 = W @ sim_w[H:] (threads 128..255)
        smem_buf[tid] = sim_w[tid];          // cache all 256 sim_w floats
        __syncthreads();
        const int row = tid & 127;
        const float* sv = smem_buf + ((tid >> 7) << 7);
        const float4* w4 = (const float4*)(attn_W + (size_t)row * H);
        float s = 0.f;
#pragma unroll
        for (int j = 0; j < 32; j++) {
            float4 w = w4[j];
            s += w.x * sv[4*j] + w.y * sv[4*j+1] + w.z * sv[4*j+2] + w.w * sv[4*j+3];
        }
        if (tid < 128) g_u1[row] = s; else g_u2[row] = s;
        __threadfence();
        __syncthreads();
        if (tid == 0) g_flag_u = gen0 + 1u;
        __syncthreads();                      // before smem_buf reuse in gemm phase
    } else if (bx == 1) {
        // Forget gate + new_slot: warp w handles slot w, fully warp-local.
        const int orr = o_rg_p[0];
        const float4* sel4 = (const float4*)(memory + (size_t)orr * (S * H) + warp * H);
        const float4* oe4  = (const float4*)o_emb_w;
        const float4* f14  = (const float4*)forget_w;
        const float4* f24  = (const float4*)(forget_w + H);
        float4 v  = sel4[lane];
        float4 oe = oe4[lane];
        float4 f1 = f14[lane];
        float4 f2 = f24[lane];
        float d = oe.x*f1.x + oe.y*f1.y + oe.z*f1.z + oe.w*f1.w
                + v.x*f2.x  + v.y*f2.y  + v.z*f2.z  + v.w*f2.w;
#pragma unroll
        for (int off = 16; off > 0; off >>= 1)
            d += __shfl_xor_sync(0xffffffffu, d, off);
        float g = 1.f / (1.f + expf(-d));
        float4 ns;
        ns.x = v.x * (1.f - g) + oe.x * g;
        ns.y = v.y * (1.f - g) + oe.y * g;
        ns.z = v.z * (1.f - g) + oe.z * g;
        ns.w = v.w * (1.f - g) + oe.w * g;
        ((float4*)g_new_slot)[warp * 32 + lane] = ns;
        __threadfence();
        __syncthreads();
        if (tid == 0) g_flag_s = gen0 + 1u;
    }

    // ================= ATTEND (all blocks, warp-per-batch) =================
    {
        // Wait for prep (most blocks launch after it completes).
        while (g_flag_u != gen0 + 1u) {}
        while (g_flag_s != gen0 + 1u) {}
        __threadfence();   // acquire

        const int orr = o_rg_p[0];
        const float4 u1 = ((const float4*)g_u1)[lane];
        const float4 u2 = ((const float4*)g_u2)[lane];
        const float  c  = sim_b[0];

        for (int b = bx * NWARP + warp; b < BB; b += TOTAL_WARPS) {
            const int r = d_rg[b];
            const float4* src = (r == orr)
                ? (const float4*)g_new_slot
                : (const float4*)(memory + (size_t)r * (S * H));

            float4 km[S];
#pragma unroll
            for (int s = 0; s < S; s++) km[s] = src[s * 32 + lane];
            const float4 oer = ((const float4*)(o_emb_r + (size_t)b * H))[lane];

            float a = oer.x*u1.x + oer.y*u1.y + oer.z*u1.z + oer.w*u1.w;
            float pv[S];
#pragma unroll
            for (int s = 0; s < S; s++)
                pv[s] = km[s].x*u2.x + km[s].y*u2.y + km[s].z*u2.z + km[s].w*u2.w;

#pragma unroll
            for (int off = 16; off > 0; off >>= 1) {
                a += __shfl_down_sync(0xffffffffu, a, off);
#pragma unroll
                for (int s = 0; s < S; s++)
                    pv[s] += __shfl_down_sync(0xffffffffu, pv[s], off);
            }

            float sc[S];
            if (lane == 0) {
                float m = 0.f, l[S];
#pragma unroll
                for (int s = 0; s < S; s++) {
                    float v = a + pv[s] + c;
                    l[s] = v > 0.f ? v : 0.f;
                    m = fmaxf(m, l[s]);
                }
                float sum = 0.f;
#pragma unroll
                for (int s = 0; s < S; s++) { l[s] = expf(l[s] - m); sum += l[s]; }
                const float inv = 1.f / sum;
#pragma unroll
                for (int s = 0; s < S; s++) sc[s] = l[s] * inv;
            }
#pragma unroll
            for (int s = 0; s < S; s++) {
                float v = (lane == 0) ? sc[s] : 0.f;
                sc[s] = __shfl_sync(0xffffffffu, v, 0);
            }

            float4 ctx = make_float4(0.f, 0.f, 0.f, 0.f);
#pragma unroll
            for (int s = 0; s < S; s++) {
                ctx.x += sc[s] * km[s].x;
                ctx.y += sc[s] * km[s].y;
                ctx.z += sc[s] * km[s].z;
                ctx.w += sc[s] * km[s].w;
            }
            ((float4*)(g_ctx + (size_t)b * H))[lane] = ctx;
        }
    }

    // Prefetch first half of W into smem (independent of ctx) to hide it
    // under the grid barrier.
    float* Ws = smem_buf;             // [64][H]  (32KB)
    float* Cs = smem_buf + 64 * H;    // [32][H]  (16KB)
    if (bx < 128) {
        const float4* W4  = (const float4*)attn_W;
        float4*       Ws4 = (float4*)Ws;
#pragma unroll
        for (int i = 0; i < 8; i++) Ws4[tid + i * 256] = W4[tid + i * 256];
    }

    // ================= GRID BARRIER =================
    __threadfence();          // publish ctx stores (each thread)
    __syncthreads();
    if (tid == 0) {
        unsigned n = atomicAdd(&g_bar_cnt, 1u);
        if (n == GRID - 1u) {
            g_bar_cnt = 0u;
            __threadfence();
            g_gen = gen0 + 1u;     // release
        } else {
            while (g_gen == gen0) {}
        }
        __threadfence();           // acquire
    }
    __syncthreads();

    // ================= GEMM: out = ctx @ W  (blocks 0..127) =================
    if (bx < 128) {
        const int row0 = bx * 32;

        // Load ctx tile (32 x 128 = 1024 float4).
        const float4* C4  = (const float4*)(g_ctx + (size_t)row0 * H);
        float4*       Cs4 = (float4*)Cs;
        Cs4[tid]       = C4[tid];
        Cs4[tid + 256] = C4[tid + 256];
        Cs4[tid + 512] = C4[tid + 512];
        Cs4[tid + 768] = C4[tid + 768];

        const int tc = tid & 31;
        const int r0 = (tid >> 5) << 2;

        float acc[4][4] = {};

#pragma unroll
        for (int kt = 0; kt < 2; kt++) {
            if (kt) {
                __syncthreads();   // previous Ws reads done
                const float4* W4  = (const float4*)(attn_W + 64 * H);
                float4*       Ws4 = (float4*)Ws;
#pragma unroll
                for (int i = 0; i < 8; i++) Ws4[tid + i * 256] = W4[tid + i * 256];
            }
            __syncthreads();       // Ws (+Cs at kt=0) visible

#pragma unroll 4
            for (int k = 0; k < 64; k++) {
                float4 wv = ((const float4*)(Ws + k * H))[tc];
#pragma unroll
                for (int rr = 0; rr < 4; rr++) {
                    float cv = Cs[(r0 + rr) * H + kt * 64 + k];
                    acc[rr][0] += cv * wv.x;
                    acc[rr][1] += cv * wv.y;
                    acc[rr][2] += cv * wv.z;
                    acc[rr][3] += cv * wv.w;
                }
            }
        }

#pragma unroll
        for (int rr = 0; rr < 4; rr++) {
            float4 v = make_float4(acc[rr][0], acc[rr][1], acc[rr][2], acc[rr][3]);
            ((float4*)(out + (size_t)(row0 + r0 + rr) * H))[tc] = v;
        }
    }
}

// ---------------------------------------------------------------------------
extern "C" void kernel_launch(void* const* d_in, const int* in_sizes, int n_in,
                              void* d_out, int out_size)
{
    const float* memory   = (const float*)d_in[0];
    const float* o_emb_w  = (const float*)d_in[1];
    const float* o_emb_r  = (const float*)d_in[2];
    const float* attn_W   = (const float*)d_in[3];
    const float* sim_w    = (const float*)d_in[4];
    const float* sim_b    = (const float*)d_in[5];
    const float* forget_w = (const float*)d_in[6];
    const int*   o_rg     = (const int*)d_in[7];
    const int*   d_rg     = (const int*)d_in[8];
    float* out = (float*)d_out;

    fused_kernel<<<GRID, 256>>>(memory, o_emb_w, o_emb_r, attn_W, sim_w, sim_b,
                                forget_w, o_rg, d_rg, out);
}

// round 4
// speedup vs baseline: 1.5702x; 1.5702x over previous
#include <cuda_runtime.h>
#include <math.h>

#define S    8
#define H    128
#define BB   4096
#define NBLK 128     // 32 batches (= 32 output rows) per block

__global__ __launch_bounds__(256)
void fused_kernel(const float* __restrict__ memory,
                  const float* __restrict__ o_emb_w,
                  const float* __restrict__ o_emb_r,
                  const float* __restrict__ attn_W,
                  const float* __restrict__ sim_w,
                  const float* __restrict__ sim_b,
                  const float* __restrict__ forget_w,
                  const int*   __restrict__ o_rg_p,
                  const int*   __restrict__ d_rg,
                  float*       __restrict__ out)
{
    // 48KB static smem, time-shared:
    //   phase 1/2: ns[8][128] + u1s[128] + u2s[128] live in the Ws region
    //   phase 3  : Ws[64][128] (W half) ; Cs[32][128] (ctx) lives throughout
    __shared__ float sm[64 * H + 32 * H];
    float* Ws  = sm;
    float* Cs  = sm + 64 * H;
    float* ns  = sm;                 // [S][H]
    float* u1s = sm + S * H;         // [H]
    float* u2s = sm + S * H + H;     // [H]

    const int tid  = threadIdx.x;
    const int warp = tid >> 5;
    const int lane = tid & 31;
    const int orr  = o_rg_p[0];

    // ============ PREP (redundant per block; all data L2-resident) ============
    // Gate + new_slot: warp w handles slot w, fully warp-local.
    {
        const float4* sel4 = (const float4*)(memory + (size_t)orr * (S * H) + warp * H);
        float4 v  = sel4[lane];
        float4 oe = ((const float4*)o_emb_w)[lane];
        float4 f1 = ((const float4*)forget_w)[lane];
        float4 f2 = ((const float4*)(forget_w + H))[lane];
        float d = oe.x*f1.x + oe.y*f1.y + oe.z*f1.z + oe.w*f1.w
                + v.x*f2.x  + v.y*f2.y  + v.z*f2.z  + v.w*f2.w;
#pragma unroll
        for (int off = 16; off > 0; off >>= 1)
            d += __shfl_xor_sync(0xffffffffu, d, off);
        float g = 1.f / (1.f + __expf(-d));
        float4 nv;
        nv.x = v.x + (oe.x - v.x) * g;
        nv.y = v.y + (oe.y - v.y) * g;
        nv.z = v.z + (oe.z - v.z) * g;
        nv.w = v.w + (oe.w - v.w) * g;
        ((float4*)ns)[warp * 32 + lane] = nv;
    }

    // u1 = W @ sim_w[:H], u2 = W @ sim_w[H:]; warp computes 16 rows, 2 per iter.
    {
        const float4 sw1 = ((const float4*)sim_w)[lane];
        const float4 sw2 = ((const float4*)sim_w)[32 + lane];
#pragma unroll
        for (int r = 0; r < 16; r += 2) {
            const int rowA = warp * 16 + r;
            const int rowB = rowA + 1;
            float4 wa = ((const float4*)(attn_W + (size_t)rowA * H))[lane];
            float4 wb = ((const float4*)(attn_W + (size_t)rowB * H))[lane];
            float a1 = wa.x*sw1.x + wa.y*sw1.y + wa.z*sw1.z + wa.w*sw1.w;
            float a2 = wa.x*sw2.x + wa.y*sw2.y + wa.z*sw2.z + wa.w*sw2.w;
            float b1 = wb.x*sw1.x + wb.y*sw1.y + wb.z*sw1.z + wb.w*sw1.w;
            float b2 = wb.x*sw2.x + wb.y*sw2.y + wb.z*sw2.z + wb.w*sw2.w;
#pragma unroll
            for (int off = 16; off > 0; off >>= 1) {
                a1 += __shfl_xor_sync(0xffffffffu, a1, off);
                a2 += __shfl_xor_sync(0xffffffffu, a2, off);
                b1 += __shfl_xor_sync(0xffffffffu, b1, off);
                b2 += __shfl_xor_sync(0xffffffffu, b2, off);
            }
            if (lane == 0) {
                u1s[rowA] = a1; u2s[rowA] = a2;
                u1s[rowB] = b1; u2s[rowB] = b2;
            }
        }
    }
    __syncthreads();

    // ============ ATTEND: warp-per-batch, 2-batch ILP, ctx -> Cs ============
    {
        const float4 u1v = ((const float4*)u1s)[lane];
        const float4 u2v = ((const float4*)u2s)[lane];
        const float  c   = sim_b[0];
        const float4* ns4 = (const float4*)ns;
        const int base = blockIdx.x * 32 + warp * 4;

#pragma unroll
        for (int p = 0; p < 2; p++) {
            const int bA = base + 2 * p;
            const int bB = bA + 1;
            const int rA = d_rg[bA];
            const int rB = d_rg[bB];
            const float4* sA = (const float4*)(memory + (size_t)rA * (S * H));
            const float4* sB = (const float4*)(memory + (size_t)rB * (S * H));

            float4 kmA[S], kmB[S];
#pragma unroll
            for (int s = 0; s < S; s++) kmA[s] = sA[s * 32 + lane];
#pragma unroll
            for (int s = 0; s < S; s++) kmB[s] = sB[s * 32 + lane];
            float4 oA = ((const float4*)(o_emb_r + (size_t)bA * H))[lane];
            float4 oB = ((const float4*)(o_emb_r + (size_t)bB * H))[lane];

            if (rA == orr) {
#pragma unroll
                for (int s = 0; s < S; s++) kmA[s] = ns4[s * 32 + lane];
            }
            if (rB == orr) {
#pragma unroll
                for (int s = 0; s < S; s++) kmB[s] = ns4[s * 32 + lane];
            }

            float aA = oA.x*u1v.x + oA.y*u1v.y + oA.z*u1v.z + oA.w*u1v.w;
            float aB = oB.x*u1v.x + oB.y*u1v.y + oB.z*u1v.z + oB.w*u1v.w;
            float pA[S], pB[S];
#pragma unroll
            for (int s = 0; s < S; s++) {
                pA[s] = kmA[s].x*u2v.x + kmA[s].y*u2v.y + kmA[s].z*u2v.z + kmA[s].w*u2v.w;
                pB[s] = kmB[s].x*u2v.x + kmB[s].y*u2v.y + kmB[s].z*u2v.z + kmB[s].w*u2v.w;
            }
#pragma unroll
            for (int off = 16; off > 0; off >>= 1) {
                aA += __shfl_xor_sync(0xffffffffu, aA, off);
                aB += __shfl_xor_sync(0xffffffffu, aB, off);
#pragma unroll
                for (int s = 0; s < S; s++) {
                    pA[s] += __shfl_xor_sync(0xffffffffu, pA[s], off);
                    pB[s] += __shfl_xor_sync(0xffffffffu, pB[s], off);
                }
            }

            // softmax(relu(a + p + c)) computed redundantly on all lanes
            float scA[S], scB[S];
            {
                float m = 0.f;
#pragma unroll
                for (int s = 0; s < S; s++) {
                    float v = aA + pA[s] + c;
                    scA[s] = v > 0.f ? v : 0.f;
                    m = fmaxf(m, scA[s]);
                }
                float sum = 0.f;
#pragma unroll
                for (int s = 0; s < S; s++) { scA[s] = __expf(scA[s] - m); sum += scA[s]; }
                float inv = 1.f / sum;
#pragma unroll
                for (int s = 0; s < S; s++) scA[s] *= inv;
            }
            {
                float m = 0.f;
#pragma unroll
                for (int s = 0; s < S; s++) {
                    float v = aB + pB[s] + c;
                    scB[s] = v > 0.f ? v : 0.f;
                    m = fmaxf(m, scB[s]);
                }
                float sum = 0.f;
#pragma unroll
                for (int s = 0; s < S; s++) { scB[s] = __expf(scB[s] - m); sum += scB[s]; }
                float inv = 1.f / sum;
#pragma unroll
                for (int s = 0; s < S; s++) scB[s] *= inv;
            }

            float4 cA = make_float4(0.f, 0.f, 0.f, 0.f);
            float4 cB = make_float4(0.f, 0.f, 0.f, 0.f);
#pragma unroll
            for (int s = 0; s < S; s++) {
                cA.x += scA[s] * kmA[s].x;  cA.y += scA[s] * kmA[s].y;
                cA.z += scA[s] * kmA[s].z;  cA.w += scA[s] * kmA[s].w;
                cB.x += scB[s] * kmB[s].x;  cB.y += scB[s] * kmB[s].y;
                cB.z += scB[s] * kmB[s].z;  cB.w += scB[s] * kmB[s].w;
            }
            ((float4*)(Cs + (warp * 4 + 2 * p)     * H))[lane] = cA;
            ((float4*)(Cs + (warp * 4 + 2 * p + 1) * H))[lane] = cB;
        }
    }

    // ============ GEMM: out[row0..row0+32) = Cs @ W ============
    const int row0 = blockIdx.x * 32;
    const int tc   = tid & 31;        // cols tc*4 .. tc*4+3
    const int r0   = (tid >> 5) << 2; // rows r0 .. r0+3

    float4 acc[4];
#pragma unroll
    for (int rr = 0; rr < 4; rr++) acc[rr] = make_float4(0.f, 0.f, 0.f, 0.f);

#pragma unroll
    for (int kt = 0; kt < 2; kt++) {
        __syncthreads();  // attend smem reads done (kt=0) / prior Ws reads done (kt=1)
        {
            const float4* W4  = (const float4*)(attn_W + (size_t)kt * 64 * H);
            float4*       Ws4 = (float4*)Ws;
#pragma unroll
            for (int i = 0; i < 8; i++) Ws4[tid + i * 256] = W4[tid + i * 256];
        }
        __syncthreads();

#pragma unroll 2
        for (int kq = 0; kq < 16; kq++) {
            const int k = kq * 4;
            float4 wv0 = ((const float4*)(Ws + (k + 0) * H))[tc];
            float4 wv1 = ((const float4*)(Ws + (k + 1) * H))[tc];
            float4 wv2 = ((const float4*)(Ws + (k + 2) * H))[tc];
            float4 wv3 = ((const float4*)(Ws + (k + 3) * H))[tc];
#pragma unroll
            for (int rr = 0; rr < 4; rr++) {
                float4 cv = *(const float4*)(Cs + (r0 + rr) * H + kt * 64 + k);
                acc[rr].x += cv.x * wv0.x; acc[rr].y += cv.x * wv0.y;
                acc[rr].z += cv.x * wv0.z; acc[rr].w += cv.x * wv0.w;
                acc[rr].x += cv.y * wv1.x; acc[rr].y += cv.y * wv1.y;
                acc[rr].z += cv.y * wv1.z; acc[rr].w += cv.y * wv1.w;
                acc[rr].x += cv.z * wv2.x; acc[rr].y += cv.z * wv2.y;
                acc[rr].z += cv.z * wv2.z; acc[rr].w += cv.z * wv2.w;
                acc[rr].x += cv.w * wv3.x; acc[rr].y += cv.w * wv3.y;
                acc[rr].z += cv.w * wv3.z; acc[rr].w += cv.w * wv3.w;
            }
        }
    }

#pragma unroll
    for (int rr = 0; rr < 4; rr++)
        ((float4*)(out + (size_t)(row0 + r0 + rr) * H))[tc] = acc[rr];
}

// ---------------------------------------------------------------------------
extern "C" void kernel_launch(void* const* d_in, const int* in_sizes, int n_in,
                              void* d_out, int out_size)
{
    const float* memory   = (const float*)d_in[0];
    const float* o_emb_w  = (const float*)d_in[1];
    const float* o_emb_r  = (const float*)d_in[2];
    const float* attn_W   = (const float*)d_in[3];
    const float* sim_w    = (const float*)d_in[4];
    const float* sim_b    = (const float*)d_in[5];
    const float* forget_w = (const float*)d_in[6];
    const int*   o_rg     = (const int*)d_in[7];
    const int*   d_rg     = (const int*)d_in[8];
    float* out = (float*)d_out;

    fused_kernel<<<NBLK, 256>>>(memory, o_emb_w, o_emb_r, attn_W, sim_w, sim_b,
                                forget_w, o_rg, d_rg, out);
}

// round 5
// speedup vs baseline: 1.7732x; 1.1293x over previous
#include <cuda_runtime.h>
#include <math.h>

#define S    8
#define H    128
#define BB   4096
#define NBLK 128     // 32 batches (= 32 output rows) per block
#define NT   512

// ---- packed f32x2 helpers (ptxas never auto-fuses; PTX only) ----
__device__ __forceinline__ unsigned long long pk2(float lo, float hi) {
    unsigned long long r;
    asm("mov.b64 %0, {%1, %2};" : "=l"(r) : "f"(lo), "f"(hi));
    return r;
}
__device__ __forceinline__ void upk2(float& lo, float& hi, unsigned long long v) {
    asm("mov.b64 {%0, %1}, %2;" : "=f"(lo), "=f"(hi) : "l"(v));
}
__device__ __forceinline__ unsigned long long fma2(unsigned long long a,
                                                   unsigned long long b,
                                                   unsigned long long c) {
    unsigned long long d;
    asm("fma.rn.f32x2 %0, %1, %2, %3;" : "=l"(d) : "l"(a), "l"(b), "l"(c));
    return d;
}

__global__ __launch_bounds__(NT)
void fused_kernel(const float* __restrict__ memory,
                  const float* __restrict__ o_emb_w,
                  const float* __restrict__ o_emb_r,
                  const float* __restrict__ attn_W,
                  const float* __restrict__ sim_w,
                  const float* __restrict__ sim_b,
                  const float* __restrict__ forget_w,
                  const int*   __restrict__ o_rg_p,
                  const int*   __restrict__ d_rg,
                  float*       __restrict__ out)
{
    // 48KB static smem, time-shared:
    //   phase 1/2: ns[8][128] + u1s[128] + u2s[128] live in the Ws region
    //   phase 3  : Ws[64][128] (W half) ; Cs[32][128] (ctx) lives throughout
    __shared__ float sm[64 * H + 32 * H];
    float* Ws  = sm;
    float* Cs  = sm + 64 * H;
    float* ns  = sm;                 // [S][H]
    float* u1s = sm + S * H;         // [H]
    float* u2s = sm + S * H + H;     // [H]

    const int tid  = threadIdx.x;
    const int warp = tid >> 5;       // 0..15
    const int lane = tid & 31;
    const int orr  = o_rg_p[0];

    // ============ PREP (redundant per block; all data L2-resident) ============
    // Gate + new_slot: warps 0..7, warp w handles slot w, fully warp-local.
    if (warp < 8) {
        const float4* sel4 = (const float4*)(memory + (size_t)orr * (S * H) + warp * H);
        float4 v  = sel4[lane];
        float4 oe = ((const float4*)o_emb_w)[lane];
        float4 f1 = ((const float4*)forget_w)[lane];
        float4 f2 = ((const float4*)(forget_w + H))[lane];
        float d = oe.x*f1.x + oe.y*f1.y + oe.z*f1.z + oe.w*f1.w
                + v.x*f2.x  + v.y*f2.y  + v.z*f2.z  + v.w*f2.w;
#pragma unroll
        for (int off = 16; off > 0; off >>= 1)
            d += __shfl_xor_sync(0xffffffffu, d, off);
        float g = 1.f / (1.f + __expf(-d));
        float4 nv;
        nv.x = v.x + (oe.x - v.x) * g;
        nv.y = v.y + (oe.y - v.y) * g;
        nv.z = v.z + (oe.z - v.z) * g;
        nv.w = v.w + (oe.w - v.w) * g;
        ((float4*)ns)[warp * 32 + lane] = nv;
    }

    // u1 = W @ sim_w[:H], u2 = W @ sim_w[H:]; 16 warps x 8 rows, 2 per iter.
    {
        const float4 sw1 = ((const float4*)sim_w)[lane];
        const float4 sw2 = ((const float4*)sim_w)[32 + lane];
#pragma unroll
        for (int r = 0; r < 8; r += 2) {
            const int rowA = warp * 8 + r;
            const int rowB = rowA + 1;
            float4 wa = ((const float4*)(attn_W + (size_t)rowA * H))[lane];
            float4 wb = ((const float4*)(attn_W + (size_t)rowB * H))[lane];
            float a1 = wa.x*sw1.x + wa.y*sw1.y + wa.z*sw1.z + wa.w*sw1.w;
            float a2 = wa.x*sw2.x + wa.y*sw2.y + wa.z*sw2.z + wa.w*sw2.w;
            float b1 = wb.x*sw1.x + wb.y*sw1.y + wb.z*sw1.z + wb.w*sw1.w;
            float b2 = wb.x*sw2.x + wb.y*sw2.y + wb.z*sw2.z + wb.w*sw2.w;
#pragma unroll
            for (int off = 16; off > 0; off >>= 1) {
                a1 += __shfl_xor_sync(0xffffffffu, a1, off);
                a2 += __shfl_xor_sync(0xffffffffu, a2, off);
                b1 += __shfl_xor_sync(0xffffffffu, b1, off);
                b2 += __shfl_xor_sync(0xffffffffu, b2, off);
            }
            if (lane == 0) {
                u1s[rowA] = a1; u2s[rowA] = a2;
                u1s[rowB] = b1; u2s[rowB] = b2;
            }
        }
    }
    __syncthreads();

    // ============ ATTEND: 16 warps x 2 batches (ILP pair), ctx -> Cs ============
    {
        const float4 u1v = ((const float4*)u1s)[lane];
        const float4 u2v = ((const float4*)u2s)[lane];
        const float  c   = sim_b[0];
        const float4* ns4 = (const float4*)ns;

        const int bA = blockIdx.x * 32 + warp * 2;
        const int bB = bA + 1;
        const int rA = d_rg[bA];
        const int rB = d_rg[bB];
        const float4* sA = (const float4*)(memory + (size_t)rA * (S * H));
        const float4* sB = (const float4*)(memory + (size_t)rB * (S * H));

        float4 kmA[S], kmB[S];
#pragma unroll
        for (int s = 0; s < S; s++) kmA[s] = sA[s * 32 + lane];
#pragma unroll
        for (int s = 0; s < S; s++) kmB[s] = sB[s * 32 + lane];
        float4 oA = ((const float4*)(o_emb_r + (size_t)bA * H))[lane];
        float4 oB = ((const float4*)(o_emb_r + (size_t)bB * H))[lane];

        if (rA == orr) {
#pragma unroll
            for (int s = 0; s < S; s++) kmA[s] = ns4[s * 32 + lane];
        }
        if (rB == orr) {
#pragma unroll
            for (int s = 0; s < S; s++) kmB[s] = ns4[s * 32 + lane];
        }

        float aA = oA.x*u1v.x + oA.y*u1v.y + oA.z*u1v.z + oA.w*u1v.w;
        float aB = oB.x*u1v.x + oB.y*u1v.y + oB.z*u1v.z + oB.w*u1v.w;
        float pA[S], pB[S];
#pragma unroll
        for (int s = 0; s < S; s++) {
            pA[s] = kmA[s].x*u2v.x + kmA[s].y*u2v.y + kmA[s].z*u2v.z + kmA[s].w*u2v.w;
            pB[s] = kmB[s].x*u2v.x + kmB[s].y*u2v.y + kmB[s].z*u2v.z + kmB[s].w*u2v.w;
        }
#pragma unroll
        for (int off = 16; off > 0; off >>= 1) {
            aA += __shfl_xor_sync(0xffffffffu, aA, off);
            aB += __shfl_xor_sync(0xffffffffu, aB, off);
#pragma unroll
            for (int s = 0; s < S; s++) {
                pA[s] += __shfl_xor_sync(0xffffffffu, pA[s], off);
                pB[s] += __shfl_xor_sync(0xffffffffu, pB[s], off);
            }
        }

        // softmax(relu(a + p + c)) computed redundantly on all lanes
        float scA[S], scB[S];
        {
            float m = 0.f;
#pragma unroll
            for (int s = 0; s < S; s++) {
                float v = aA + pA[s] + c;
                scA[s] = v > 0.f ? v : 0.f;
                m = fmaxf(m, scA[s]);
            }
            float sum = 0.f;
#pragma unroll
            for (int s = 0; s < S; s++) { scA[s] = __expf(scA[s] - m); sum += scA[s]; }
            float inv = 1.f / sum;
#pragma unroll
            for (int s = 0; s < S; s++) scA[s] *= inv;
        }
        {
            float m = 0.f;
#pragma unroll
            for (int s = 0; s < S; s++) {
                float v = aB + pB[s] + c;
                scB[s] = v > 0.f ? v : 0.f;
                m = fmaxf(m, scB[s]);
            }
            float sum = 0.f;
#pragma unroll
            for (int s = 0; s < S; s++) { scB[s] = __expf(scB[s] - m); sum += scB[s]; }
            float inv = 1.f / sum;
#pragma unroll
            for (int s = 0; s < S; s++) scB[s] *= inv;
        }

        float4 cA = make_float4(0.f, 0.f, 0.f, 0.f);
        float4 cB = make_float4(0.f, 0.f, 0.f, 0.f);
#pragma unroll
        for (int s = 0; s < S; s++) {
            cA.x += scA[s] * kmA[s].x;  cA.y += scA[s] * kmA[s].y;
            cA.z += scA[s] * kmA[s].z;  cA.w += scA[s] * kmA[s].w;
            cB.x += scB[s] * kmB[s].x;  cB.y += scB[s] * kmB[s].y;
            cB.z += scB[s] * kmB[s].z;  cB.w += scB[s] * kmB[s].w;
        }
        ((float4*)(Cs + (warp * 2)     * H))[lane] = cA;
        ((float4*)(Cs + (warp * 2 + 1) * H))[lane] = cB;
    }

    // ============ GEMM: out[row0..row0+32) = Cs @ W  (warps 0..7) ============
    const int row0 = blockIdx.x * 32;
    const int tc   = lane;            // cols tc*4 .. tc*4+3
    const int r0   = (warp & 7) << 2; // rows r0 .. r0+3 (gemm warps only)
    const bool gw  = (warp < 8);

    unsigned long long accL[4] = {0ull, 0ull, 0ull, 0ull};  // cols {c0,c1}
    unsigned long long accH[4] = {0ull, 0ull, 0ull, 0ull};  // cols {c2,c3}

#pragma unroll
    for (int kt = 0; kt < 2; kt++) {
        __syncthreads();  // attend smem reads done (kt=0) / prior Ws reads done (kt=1)
        {
            const float4* W4  = (const float4*)(attn_W + (size_t)kt * 64 * H);
            float4*       Ws4 = (float4*)Ws;
#pragma unroll
            for (int i = 0; i < 4; i++) Ws4[tid + i * NT] = W4[tid + i * NT];
        }
        __syncthreads();

        if (gw) {
#pragma unroll 2
            for (int kq = 0; kq < 16; kq++) {
                const int k = kq * 4;
                float4 wv0 = ((const float4*)(Ws + (k + 0) * H))[tc];
                float4 wv1 = ((const float4*)(Ws + (k + 1) * H))[tc];
                float4 wv2 = ((const float4*)(Ws + (k + 2) * H))[tc];
                float4 wv3 = ((const float4*)(Ws + (k + 3) * H))[tc];
                unsigned long long w0L = pk2(wv0.x, wv0.y), w0H = pk2(wv0.z, wv0.w);
                unsigned long long w1L = pk2(wv1.x, wv1.y), w1H = pk2(wv1.z, wv1.w);
                unsigned long long w2L = pk2(wv2.x, wv2.y), w2H = pk2(wv2.z, wv2.w);
                unsigned long long w3L = pk2(wv3.x, wv3.y), w3H = pk2(wv3.z, wv3.w);
#pragma unroll
                for (int rr = 0; rr < 4; rr++) {
                    float4 cv = *(const float4*)(Cs + (r0 + rr) * H + kt * 64 + k);
                    unsigned long long c0 = pk2(cv.x, cv.x);
                    unsigned long long c1 = pk2(cv.y, cv.y);
                    unsigned long long c2 = pk2(cv.z, cv.z);
                    unsigned long long c3 = pk2(cv.w, cv.w);
                    accL[rr] = fma2(c0, w0L, accL[rr]);
                    accH[rr] = fma2(c0, w0H, accH[rr]);
                    accL[rr] = fma2(c1, w1L, accL[rr]);
                    accH[rr] = fma2(c1, w1H, accH[rr]);
                    accL[rr] = fma2(c2, w2L, accL[rr]);
                    accH[rr] = fma2(c2, w2H, accH[rr]);
                    accL[rr] = fma2(c3, w3L, accL[rr]);
                    accH[rr] = fma2(c3, w3H, accH[rr]);
                }
            }
        }
    }

    if (gw) {
#pragma unroll
        for (int rr = 0; rr < 4; rr++) {
            float4 v;
            upk2(v.x, v.y, accL[rr]);
            upk2(v.z, v.w, accH[rr]);
            ((float4*)(out + (size_t)(row0 + r0 + rr) * H))[tc] = v;
        }
    }
}

// ---------------------------------------------------------------------------
extern "C" void kernel_launch(void* const* d_in, const int* in_sizes, int n_in,
                              void* d_out, int out_size)
{
    const float* memory   = (const float*)d_in[0];
    const float* o_emb_w  = (const float*)d_in[1];
    const float* o_emb_r  = (const float*)d_in[2];
    const float* attn_W   = (const float*)d_in[3];
    const float* sim_w    = (const float*)d_in[4];
    const float* sim_b    = (const float*)d_in[5];
    const float* forget_w = (const float*)d_in[6];
    const int*   o_rg     = (const int*)d_in[7];
    const int*   d_rg     = (const int*)d_in[8];
    float* out = (float*)d_out;

    fused_kernel<<<NBLK, NT>>>(memory, o_emb_w, o_emb_r, attn_W, sim_w, sim_b,
                               forget_w, o_rg, d_rg, out);
}